// round 1
// baseline (speedup 1.0000x reference)
#include <cuda_runtime.h>
#include <math.h>

// Problem constants
#define BATCH 8
#define NTOK 1024
#define DIMC 512
#define NH 16
#define HD 32
#define TABLE_SZ 3969
#define SEQ_SCALE 6.93147180559945309f  // ln(1024)

// ---------------- scratch (device globals; no allocation allowed) -------------
__device__ float g_scale[NH];
__device__ float g_t[TABLE_SZ * NH];
__device__ float g_bias[NH * NTOK * NTOK];          // [h][n][m] 64MB
__device__ float g_qkv[BATCH * NTOK * 3 * DIMC];    // 50MB
__device__ float g_q[BATCH * NH * NTOK * HD];       // 16MB (normalized + qe, scaled)
__device__ float g_k[BATCH * NH * NTOK * HD];       // 16MB (normalized)
__device__ float g_v[BATCH * NH * NTOK * HD];       // 16MB
__device__ float g_attn[BATCH * NTOK * DIMC];       // 16MB attention output [b*n][h*32+d]

// ---------------- kernel 1: scale = softplus(temperature) * ln(N) ------------
__global__ void scale_kernel(const float* __restrict__ temp) {
    int h = threadIdx.x;
    if (h < NH) {
        float t = temp[h];
        float sp = (t > 20.0f) ? t : log1pf(expf(t));
        g_scale[h] = sp * SEQ_SCALE;
    }
}

// ---------------- kernel 2: CPB MLP  t[r][h] ---------------------------------
__global__ void cpb_kernel(const float* __restrict__ table,
                           const float* __restrict__ fc1w,
                           const float* __restrict__ fc1b,
                           const float* __restrict__ fc2w,
                           const float* __restrict__ fc2b) {
    __shared__ float hid[512];
    int r = blockIdx.x;
    int j = threadIdx.x;  // 512 threads
    float c0 = table[r * 2 + 0];
    float c1 = table[r * 2 + 1];
    float hv = c0 * fc1w[j * 2 + 0] + c1 * fc1w[j * 2 + 1] + fc1b[j];
    hid[j] = fmaxf(hv, 0.0f);
    __syncthreads();
    int w = j >> 5;       // warp = head (16 warps)
    int lane = j & 31;
    float acc = 0.0f;
#pragma unroll
    for (int kk = lane; kk < 512; kk += 32) acc += hid[kk] * fc2w[w * 512 + kk];
#pragma unroll
    for (int off = 16; off >= 1; off >>= 1) acc += __shfl_xor_sync(0xffffffffu, acc, off);
    if (lane == 0) g_t[r * NH + w] = acc + fc2b[w];
}

// ---------------- kernel 3: bias gather  bias[h][n][m] = t[rpi[n][m]][h] -----
__global__ void bias_kernel(const int* __restrict__ rpi) {
    int n = blockIdx.x;
    for (int m = threadIdx.x; m < NTOK; m += blockDim.x) {
        int idx = rpi[n * NTOK + m];
        const float4* tp = (const float4*)(g_t + idx * NH);
        float4 t0 = tp[0], t1 = tp[1], t2 = tp[2], t3 = tp[3];
        float v[16] = {t0.x, t0.y, t0.z, t0.w, t1.x, t1.y, t1.z, t1.w,
                       t2.x, t2.y, t2.z, t2.w, t3.x, t3.y, t3.z, t3.w};
#pragma unroll
        for (int h = 0; h < NH; h++)
            g_bias[(h * NTOK + n) * NTOK + m] = v[h];
    }
}

// ---------------- SGEMM (NT): C[m][o] = sum_k A[m][k]*W[o][k] + bias[o] ------
// BM=BN=128, BK=8, 256 threads, 8x8 microtile.
__global__ __launch_bounds__(256) void sgemm_nt_bias(const float* __restrict__ A,
                                                     const float* __restrict__ W,
                                                     const float* __restrict__ bias,
                                                     float* __restrict__ C,
                                                     int M, int Nn, int K) {
    __shared__ float As[8][128];
    __shared__ float Ws[8][128];
    int tid = threadIdx.x;
    int tx = tid & 15;
    int ty = tid >> 4;
    int m0 = blockIdx.y * 128;
    int n0 = blockIdx.x * 128;

    int lr = tid >> 1;          // 0..127
    int lc = (tid & 1) * 4;     // 0 or 4
    const float* Aptr = A + (size_t)(m0 + lr) * K + lc;
    const float* Wptr = W + (size_t)(n0 + lr) * K + lc;

    float acc[8][8];
#pragma unroll
    for (int i = 0; i < 8; i++)
#pragma unroll
        for (int j = 0; j < 8; j++) acc[i][j] = 0.0f;

    for (int k0 = 0; k0 < K; k0 += 8) {
        float4 av = *(const float4*)(Aptr + k0);
        float4 wv = *(const float4*)(Wptr + k0);
        __syncthreads();
        As[lc + 0][lr] = av.x; As[lc + 1][lr] = av.y;
        As[lc + 2][lr] = av.z; As[lc + 3][lr] = av.w;
        Ws[lc + 0][lr] = wv.x; Ws[lc + 1][lr] = wv.y;
        Ws[lc + 2][lr] = wv.z; Ws[lc + 3][lr] = wv.w;
        __syncthreads();
#pragma unroll
        for (int k = 0; k < 8; k++) {
            float4 a0 = *(const float4*)&As[k][ty * 4];
            float4 a1 = *(const float4*)&As[k][ty * 4 + 64];
            float4 b0 = *(const float4*)&Ws[k][tx * 4];
            float4 b1 = *(const float4*)&Ws[k][tx * 4 + 64];
            float a[8] = {a0.x, a0.y, a0.z, a0.w, a1.x, a1.y, a1.z, a1.w};
            float b[8] = {b0.x, b0.y, b0.z, b0.w, b1.x, b1.y, b1.z, b1.w};
#pragma unroll
            for (int i = 0; i < 8; i++)
#pragma unroll
                for (int j = 0; j < 8; j++) acc[i][j] += a[i] * b[j];
        }
    }
    // epilogue
    float4 bv0 = *(const float4*)(bias + n0 + tx * 4);
    float4 bv1 = *(const float4*)(bias + n0 + tx * 4 + 64);
#pragma unroll
    for (int i = 0; i < 8; i++) {
        int row = m0 + ty * 4 + (i & 3) + (i >> 2) * 64;
        float4 o0 = make_float4(acc[i][0] + bv0.x, acc[i][1] + bv0.y,
                                acc[i][2] + bv0.z, acc[i][3] + bv0.w);
        float4 o1 = make_float4(acc[i][4] + bv1.x, acc[i][5] + bv1.y,
                                acc[i][6] + bv1.z, acc[i][7] + bv1.w);
        *(float4*)(C + (size_t)row * Nn + n0 + tx * 4) = o0;
        *(float4*)(C + (size_t)row * Nn + n0 + tx * 4 + 64) = o1;
    }
}

// ---------------- reorg: split qkv, normalize q/k, repack to [b,h,n,d] -------
__global__ void reorg_kernel(const float* __restrict__ qe) {
    int wg = blockIdx.x * 8 + (threadIdx.x >> 5);  // global warp id
    int lane = threadIdx.x & 31;
    int h = wg & 15;
    int bn = wg >> 4;          // 0..8191
    int b = bn >> 10;
    int n = bn & 1023;
    const float* base = g_qkv + (size_t)bn * (3 * DIMC);
    float q = base[h * HD + lane];
    float k = base[DIMC + h * HD + lane];
    float v = base[2 * DIMC + h * HD + lane];

    float s = q * q;
#pragma unroll
    for (int off = 16; off >= 1; off >>= 1) s += __shfl_xor_sync(0xffffffffu, s, off);
    float qn = q / fmaxf(sqrtf(s), 1e-12f);
    qn = (qn + qe[h * HD + lane]) * g_scale[h];

    s = k * k;
#pragma unroll
    for (int off = 16; off >= 1; off >>= 1) s += __shfl_xor_sync(0xffffffffu, s, off);
    float kn = k / fmaxf(sqrtf(s), 1e-12f);

    size_t idx = ((size_t)(b * NH + h) * NTOK + n) * HD + lane;
    g_q[idx] = qn;
    g_k[idx] = kn;
    g_v[idx] = v;
}

// ---------------- attention: flash-style over key tiles ----------------------
// grid (N/64, H, B), 256 threads. 64 queries/block, key tiles of 64.
__global__ __launch_bounds__(256) void attn_kernel() {
    __shared__ float Qs[64][32];
    __shared__ float Ks[64][32];
    __shared__ float Vs[64][32];
    __shared__ float Ps[64][64];

    int qt = blockIdx.x;
    int h  = blockIdx.y;
    int b  = blockIdx.z;
    int tid = threadIdx.x;
    int tx = tid & 15;
    int ty = tid >> 4;

    const float* qbase = g_q + ((size_t)(b * NH + h) * NTOK + qt * 64) * HD;
    const float* kbase = g_k + (size_t)(b * NH + h) * NTOK * HD;
    const float* vbase = g_v + (size_t)(b * NH + h) * NTOK * HD;
    const float* bbase = g_bias + ((size_t)h * NTOK + qt * 64) * NTOK;

    // load Q tile: 2048 floats
    for (int i = tid; i < 64 * 32 / 4; i += 256)
        ((float4*)&Qs[0][0])[i] = ((const float4*)qbase)[i];

    float m_i[4], l_i[4], o[4][2];
#pragma unroll
    for (int i = 0; i < 4; i++) {
        m_i[i] = -INFINITY; l_i[i] = 0.0f; o[i][0] = 0.0f; o[i][1] = 0.0f;
    }

    for (int mt = 0; mt < 16; mt++) {
        __syncthreads();  // prior PV reads done before K/V/P overwrite (also covers Q store)
        for (int i = tid; i < 64 * 32 / 4; i += 256) {
            ((float4*)&Ks[0][0])[i] = ((const float4*)(kbase + mt * 64 * HD))[i];
            ((float4*)&Vs[0][0])[i] = ((const float4*)(vbase + mt * 64 * HD))[i];
        }
        __syncthreads();

        float s[4][4];
#pragma unroll
        for (int i = 0; i < 4; i++)
#pragma unroll
            for (int j = 0; j < 4; j++) s[i][j] = 0.0f;

#pragma unroll
        for (int kk = 0; kk < 8; kk++) {
            float4 qv[4], kv[4];
#pragma unroll
            for (int i = 0; i < 4; i++) qv[i] = *(const float4*)&Qs[ty * 4 + i][kk * 4];
#pragma unroll
            for (int j = 0; j < 4; j++) kv[j] = *(const float4*)&Ks[tx * 4 + j][kk * 4];
#pragma unroll
            for (int i = 0; i < 4; i++)
#pragma unroll
                for (int j = 0; j < 4; j++)
                    s[i][j] += qv[i].x * kv[j].x + qv[i].y * kv[j].y +
                               qv[i].z * kv[j].z + qv[i].w * kv[j].w;
        }
        // add relative position bias (linear reads; L2-resident)
#pragma unroll
        for (int i = 0; i < 4; i++) {
            float4 bv = *(const float4*)(bbase + (size_t)(ty * 4 + i) * NTOK + mt * 64 + tx * 4);
            s[i][0] += bv.x; s[i][1] += bv.y; s[i][2] += bv.z; s[i][3] += bv.w;
        }
        // online softmax (row groups of 16 threads, shfl reductions)
#pragma unroll
        for (int i = 0; i < 4; i++) {
            float mx = fmaxf(fmaxf(s[i][0], s[i][1]), fmaxf(s[i][2], s[i][3]));
#pragma unroll
            for (int off = 8; off >= 1; off >>= 1)
                mx = fmaxf(mx, __shfl_xor_sync(0xffffffffu, mx, off));
            float m_new = fmaxf(m_i[i], mx);
            float alpha = __expf(m_i[i] - m_new);
            m_i[i] = m_new;
            float rs = 0.0f;
#pragma unroll
            for (int j = 0; j < 4; j++) {
                s[i][j] = __expf(s[i][j] - m_new);
                rs += s[i][j];
            }
#pragma unroll
            for (int off = 8; off >= 1; off >>= 1)
                rs += __shfl_xor_sync(0xffffffffu, rs, off);
            l_i[i] = l_i[i] * alpha + rs;
            o[i][0] *= alpha;
            o[i][1] *= alpha;
        }
        // stage P
#pragma unroll
        for (int i = 0; i < 4; i++)
            *(float4*)&Ps[ty * 4 + i][tx * 4] = make_float4(s[i][0], s[i][1], s[i][2], s[i][3]);
        __syncthreads();
        // PV accumulate
#pragma unroll
        for (int m4 = 0; m4 < 16; m4++) {
            float pr[4][4];
#pragma unroll
            for (int i = 0; i < 4; i++) {
                float4 t = *(const float4*)&Ps[ty * 4 + i][m4 * 4];
                pr[i][0] = t.x; pr[i][1] = t.y; pr[i][2] = t.z; pr[i][3] = t.w;
            }
#pragma unroll
            for (int mm = 0; mm < 4; mm++) {
                float2 vv = *(const float2*)&Vs[m4 * 4 + mm][tx * 2];
#pragma unroll
                for (int i = 0; i < 4; i++) {
                    o[i][0] += pr[i][mm] * vv.x;
                    o[i][1] += pr[i][mm] * vv.y;
                }
            }
        }
    }
    // epilogue: divide by l, write [b*n][h*32+d]
#pragma unroll
    for (int i = 0; i < 4; i++) {
        int n = qt * 64 + ty * 4 + i;
        float inv = 1.0f / l_i[i];
        float2 ov = make_float2(o[i][0] * inv, o[i][1] * inv);
        *(float2*)(g_attn + ((size_t)(b * NTOK + n)) * DIMC + h * HD + tx * 2) = ov;
    }
}

// ---------------- launcher ---------------------------------------------------
extern "C" void kernel_launch(void* const* d_in, const int* in_sizes, int n_in,
                              void* d_out, int out_size) {
    const float* x       = (const float*)d_in[0];
    // d_in[1] = _h, d_in[2] = _w (unused scalars)
    const int*   rpi     = (const int*)d_in[3];
    const float* table   = (const float*)d_in[4];
    const float* qkv_w   = (const float*)d_in[5];
    const float* qkv_b   = (const float*)d_in[6];
    const float* proj_w  = (const float*)d_in[7];
    const float* proj_b  = (const float*)d_in[8];
    const float* temp    = (const float*)d_in[9];
    const float* qe      = (const float*)d_in[10];
    const float* fc1w    = (const float*)d_in[11];
    const float* fc1b    = (const float*)d_in[12];
    const float* fc2w    = (const float*)d_in[13];
    const float* fc2b    = (const float*)d_in[14];
    float* out = (float*)d_out;

    float* p_qkv;  cudaGetSymbolAddress((void**)&p_qkv,  g_qkv);
    float* p_attn; cudaGetSymbolAddress((void**)&p_attn, g_attn);

    // 1) temperature -> scale
    scale_kernel<<<1, 32>>>(temp);
    // 2) CPB MLP
    cpb_kernel<<<TABLE_SZ, 512>>>(table, fc1w, fc1b, fc2w, fc2b);
    // 3) bias gather [H][N][N]
    bias_kernel<<<NTOK, 256>>>(rpi);
    // 4) qkv GEMM: [8192 x 1536] = x[8192 x 512] @ qkv_w^T
    {
        dim3 grid(3 * DIMC / 128, BATCH * NTOK / 128);
        sgemm_nt_bias<<<grid, 256>>>(x, qkv_w, qkv_b, p_qkv,
                                     BATCH * NTOK, 3 * DIMC, DIMC);
    }
    // 5) reorg + normalize
    reorg_kernel<<<BATCH * NTOK * NH / 8, 256>>>(qe);
    // 6) attention
    {
        dim3 grid(NTOK / 64, NH, BATCH);
        attn_kernel<<<grid, 256>>>();
    }
    // 7) output projection -> d_out
    {
        dim3 grid(DIMC / 128, BATCH * NTOK / 128);
        sgemm_nt_bias<<<grid, 256>>>(p_attn, proj_w, proj_b, out,
                                     BATCH * NTOK, DIMC, DIMC);
    }
}

// round 2
// speedup vs baseline: 2.1039x; 2.1039x over previous
#include <cuda_runtime.h>
#include <math.h>

// Problem constants
#define BATCH 8
#define NTOK 1024
#define DIMC 512
#define NH 16
#define HD 32
#define TABLE_SZ 3969
#define SEQ_SCALE 6.93147180559945309f  // ln(1024)

// ---------------- scratch (device globals; no allocation allowed) -------------
__device__ float g_scale[NH];
__device__ float g_t[TABLE_SZ * NH];
__device__ float g_bias[NH * NTOK * NTOK];          // [h][n][m] 64MB
__device__ float g_qkv[BATCH * NTOK * 3 * DIMC];    // 50MB
__device__ float g_q[BATCH * NH * NTOK * HD];       // 16MB (normalized + qe, scaled)
__device__ float g_k[BATCH * NH * NTOK * HD];       // 16MB (normalized)
__device__ float g_v[BATCH * NH * NTOK * HD];       // 16MB
__device__ float g_attn[BATCH * NTOK * DIMC];       // 16MB attention output

// ---------------- tf32 helpers ------------------------------------------------
__device__ __forceinline__ unsigned tf32_rna(float x) {
    unsigned r; asm("cvt.rna.tf32.f32 %0, %1;" : "=r"(r) : "f"(x)); return r;
}
__device__ __forceinline__ void tf32_split(float x, unsigned& hi, unsigned& lo) {
    hi = tf32_rna(x);
    lo = tf32_rna(x - __uint_as_float(hi));
}
__device__ __forceinline__ void mma8(float* c, const unsigned* a, const unsigned* b) {
    asm volatile("mma.sync.aligned.m16n8k8.row.col.f32.tf32.tf32.f32 "
                 "{%0,%1,%2,%3}, {%4,%5,%6,%7}, {%8,%9}, {%0,%1,%2,%3};"
                 : "+f"(c[0]), "+f"(c[1]), "+f"(c[2]), "+f"(c[3])
                 : "r"(a[0]), "r"(a[1]), "r"(a[2]), "r"(a[3]),
                   "r"(b[0]), "r"(b[1]));
}

// ---------------- kernel 1: scale = softplus(temperature) * ln(N) ------------
__global__ void scale_kernel(const float* __restrict__ temp) {
    int h = threadIdx.x;
    if (h < NH) {
        float t = temp[h];
        float sp = (t > 20.0f) ? t : log1pf(expf(t));
        g_scale[h] = sp * SEQ_SCALE;
    }
}

// ---------------- kernel 2: CPB MLP  t[r][h] ---------------------------------
__global__ void cpb_kernel(const float* __restrict__ table,
                           const float* __restrict__ fc1w,
                           const float* __restrict__ fc1b,
                           const float* __restrict__ fc2w,
                           const float* __restrict__ fc2b) {
    __shared__ float hid[512];
    int r = blockIdx.x;
    int j = threadIdx.x;
    float c0 = table[r * 2 + 0];
    float c1 = table[r * 2 + 1];
    float hv = c0 * fc1w[j * 2 + 0] + c1 * fc1w[j * 2 + 1] + fc1b[j];
    hid[j] = fmaxf(hv, 0.0f);
    __syncthreads();
    int w = j >> 5;
    int lane = j & 31;
    float acc = 0.0f;
#pragma unroll
    for (int kk = lane; kk < 512; kk += 32) acc += hid[kk] * fc2w[w * 512 + kk];
#pragma unroll
    for (int off = 16; off >= 1; off >>= 1) acc += __shfl_xor_sync(0xffffffffu, acc, off);
    if (lane == 0) g_t[r * NH + w] = acc + fc2b[w];
}

// ---------------- kernel 3: bias gather  bias[h][n][m] = t[rpi[n][m]][h] -----
__global__ void bias_kernel(const int* __restrict__ rpi) {
    int n = blockIdx.x;
    for (int m = threadIdx.x; m < NTOK; m += blockDim.x) {
        int idx = rpi[n * NTOK + m];
        const float4* tp = (const float4*)(g_t + idx * NH);
        float4 t0 = tp[0], t1 = tp[1], t2 = tp[2], t3 = tp[3];
        float v[16] = {t0.x, t0.y, t0.z, t0.w, t1.x, t1.y, t1.z, t1.w,
                       t2.x, t2.y, t2.z, t2.w, t3.x, t3.y, t3.z, t3.w};
#pragma unroll
        for (int h = 0; h < NH; h++)
            g_bias[(h * NTOK + n) * NTOK + m] = v[h];
    }
}

// ---------------- 3xTF32 GEMM (NT): C[m][n] = sum_k A[m][k]*W[n][k] + bias ---
// BM=BN=128, BK=16, 256 threads, 8 warps in 4x2, warp tile 32x64.
__global__ __launch_bounds__(256) void gemm3_tf32(const float* __restrict__ A,
                                                  const float* __restrict__ W,
                                                  const float* __restrict__ bias,
                                                  float* __restrict__ C,
                                                  int M, int Nn, int K) {
    __shared__ unsigned Ash[128][20], Asl[128][20], Wsh[128][20], Wsl[128][20];
    int tid = threadIdx.x;
    int wid = tid >> 5, lane = tid & 31;
    int g = lane >> 2, tg = lane & 3;
    int wm = wid & 3, wn = wid >> 2;
    int m0 = blockIdx.y * 128, n0 = blockIdx.x * 128;

    int lkc = tid & 3;       // float4 col (k/4)
    int lr = tid >> 2;       // 0..63
    const float* Ap0 = A + (size_t)(m0 + lr) * K + lkc * 4;
    const float* Ap1 = Ap0 + (size_t)64 * K;
    const float* Wp0 = W + (size_t)(n0 + lr) * K + lkc * 4;
    const float* Wp1 = Wp0 + (size_t)64 * K;

    float acc[2][8][4];
#pragma unroll
    for (int mi = 0; mi < 2; mi++)
#pragma unroll
        for (int j = 0; j < 8; j++)
#pragma unroll
            for (int c = 0; c < 4; c++) acc[mi][j][c] = 0.0f;

    float4 pa0 = *(const float4*)Ap0;
    float4 pa1 = *(const float4*)Ap1;
    float4 pw0 = *(const float4*)Wp0;
    float4 pw1 = *(const float4*)Wp1;

    for (int k0 = 0; k0 < K; k0 += 16) {
        __syncthreads();
        {
            float av[8] = {pa0.x, pa0.y, pa0.z, pa0.w, pa1.x, pa1.y, pa1.z, pa1.w};
            float wv[8] = {pw0.x, pw0.y, pw0.z, pw0.w, pw1.x, pw1.y, pw1.z, pw1.w};
#pragma unroll
            for (int i = 0; i < 4; i++) {
                unsigned h, l;
                tf32_split(av[i], h, l);
                Ash[lr][lkc * 4 + i] = h; Asl[lr][lkc * 4 + i] = l;
                tf32_split(av[i + 4], h, l);
                Ash[lr + 64][lkc * 4 + i] = h; Asl[lr + 64][lkc * 4 + i] = l;
                tf32_split(wv[i], h, l);
                Wsh[lr][lkc * 4 + i] = h; Wsl[lr][lkc * 4 + i] = l;
                tf32_split(wv[i + 4], h, l);
                Wsh[lr + 64][lkc * 4 + i] = h; Wsl[lr + 64][lkc * 4 + i] = l;
            }
        }
        __syncthreads();
        if (k0 + 16 < K) {
            pa0 = *(const float4*)(Ap0 + k0 + 16);
            pa1 = *(const float4*)(Ap1 + k0 + 16);
            pw0 = *(const float4*)(Wp0 + k0 + 16);
            pw1 = *(const float4*)(Wp1 + k0 + 16);
        }
#pragma unroll
        for (int kt = 0; kt < 2; kt++) {
            unsigned ah[2][4], al[2][4];
#pragma unroll
            for (int mi = 0; mi < 2; mi++) {
                int r = wm * 32 + mi * 16 + g;
                int kc = kt * 8 + tg;
                ah[mi][0] = Ash[r][kc];     al[mi][0] = Asl[r][kc];
                ah[mi][1] = Ash[r + 8][kc]; al[mi][1] = Asl[r + 8][kc];
                ah[mi][2] = Ash[r][kc + 4]; al[mi][2] = Asl[r][kc + 4];
                ah[mi][3] = Ash[r + 8][kc + 4]; al[mi][3] = Asl[r + 8][kc + 4];
            }
#pragma unroll
            for (int j = 0; j < 8; j++) {
                int col = wn * 64 + j * 8 + g;
                int kc = kt * 8 + tg;
                unsigned bh[2] = {Wsh[col][kc], Wsh[col][kc + 4]};
                unsigned bl[2] = {Wsl[col][kc], Wsl[col][kc + 4]};
#pragma unroll
                for (int mi = 0; mi < 2; mi++) {
                    mma8(acc[mi][j], ah[mi], bh);
                    mma8(acc[mi][j], ah[mi], bl);
                    mma8(acc[mi][j], al[mi], bh);
                }
            }
        }
    }
    // epilogue
#pragma unroll
    for (int j = 0; j < 8; j++) {
        int col = n0 + wn * 64 + j * 8 + tg * 2;
        float2 bv = *(const float2*)(bias + col);
#pragma unroll
        for (int mi = 0; mi < 2; mi++) {
            int row = m0 + wm * 32 + mi * 16 + g;
            float2 o0 = make_float2(acc[mi][j][0] + bv.x, acc[mi][j][1] + bv.y);
            float2 o1 = make_float2(acc[mi][j][2] + bv.x, acc[mi][j][3] + bv.y);
            *(float2*)(C + (size_t)row * Nn + col) = o0;
            *(float2*)(C + (size_t)(row + 8) * Nn + col) = o1;
        }
    }
}

// ---------------- reorg: split qkv, normalize q/k, repack to [b,h,n,d] -------
__global__ void reorg_kernel(const float* __restrict__ qe) {
    int wg = blockIdx.x * 8 + (threadIdx.x >> 5);
    int lane = threadIdx.x & 31;
    int h = wg & 15;
    int bn = wg >> 4;
    int b = bn >> 10;
    int n = bn & 1023;
    const float* base = g_qkv + (size_t)bn * (3 * DIMC);
    float q = base[h * HD + lane];
    float k = base[DIMC + h * HD + lane];
    float v = base[2 * DIMC + h * HD + lane];

    float s = q * q;
#pragma unroll
    for (int off = 16; off >= 1; off >>= 1) s += __shfl_xor_sync(0xffffffffu, s, off);
    float qn = q / fmaxf(sqrtf(s), 1e-12f);
    qn = (qn + qe[h * HD + lane]) * g_scale[h];

    s = k * k;
#pragma unroll
    for (int off = 16; off >= 1; off >>= 1) s += __shfl_xor_sync(0xffffffffu, s, off);
    float kn = k / fmaxf(sqrtf(s), 1e-12f);

    size_t idx = ((size_t)(b * NH + h) * NTOK + n) * HD + lane;
    g_q[idx] = qn;
    g_k[idx] = kn;
    g_v[idx] = v;
}

// ---------------- attention: flash-style, tensor-core (3xTF32 QK, TF32 PV) ---
// grid (B, N/128, H), 256 threads (8 warps), 128 queries/block, key tiles 64.
// dyn smem: Ksh[64][36], Ksl[64][36], Vs[64][36] (tf32), BP[128][68] (bias/P)
#define ATTN_SMEM ((64 * 36 * 3 + 128 * 68) * 4)
__global__ __launch_bounds__(256) void attn3_kernel() {
    extern __shared__ float sm[];
    unsigned* Ksh = (unsigned*)sm;
    unsigned* Ksl = Ksh + 64 * 36;
    unsigned* Vs = Ksl + 64 * 36;
    float* BP = (float*)(Vs + 64 * 36);
    unsigned* BPu = (unsigned*)BP;

    int b = blockIdx.x, qt = blockIdx.y, h = blockIdx.z;
    int tid = threadIdx.x;
    int w = tid >> 5, lane = tid & 31;
    int g = lane >> 2, tg = lane & 3;

    const float* qb = g_q + ((size_t)(b * NH + h) * NTOK + qt * 128) * HD;
    const float* kbase = g_k + (size_t)(b * NH + h) * NTOK * HD;
    const float* vbase = g_v + (size_t)(b * NH + h) * NTOK * HD;
    const float* bbase = g_bias + ((size_t)h * NTOK + qt * 128) * NTOK;

    // Q fragments (persist in registers), 3xTF32 split
    unsigned Qh[4][4], Ql[4][4];
#pragma unroll
    for (int kt = 0; kt < 4; kt++) {
        int c = kt * 8 + tg;
        int r = w * 16 + g;
        tf32_split(qb[r * HD + c], Qh[kt][0], Ql[kt][0]);
        tf32_split(qb[(r + 8) * HD + c], Qh[kt][1], Ql[kt][1]);
        tf32_split(qb[r * HD + c + 4], Qh[kt][2], Ql[kt][2]);
        tf32_split(qb[(r + 8) * HD + c + 4], Qh[kt][3], Ql[kt][3]);
    }

    float m0 = -INFINITY, m1 = -INFINITY, l0 = 0.0f, l1 = 0.0f;
    float O[4][4];
#pragma unroll
    for (int j = 0; j < 4; j++)
#pragma unroll
        for (int c = 0; c < 4; c++) O[j][c] = 0.0f;

    int kc8 = tid & 7, kr = tid >> 3;   // K/V loaders
    int bc = tid & 15, br = tid >> 4;   // bias loaders

    for (int mt = 0; mt < 16; mt++) {
        __syncthreads();
        // cooperative loads: K (split), V (tf32), bias (fp32)
#pragma unroll
        for (int p = 0; p < 2; p++) {
            int key = kr + p * 32;
            float4 kv = *(const float4*)(kbase + (size_t)(mt * 64 + key) * HD + kc8 * 4);
            float4 vv = *(const float4*)(vbase + (size_t)(mt * 64 + key) * HD + kc8 * 4);
            float ka[4] = {kv.x, kv.y, kv.z, kv.w};
            float va[4] = {vv.x, vv.y, vv.z, vv.w};
#pragma unroll
            for (int i = 0; i < 4; i++) {
                unsigned hh, ll;
                tf32_split(ka[i], hh, ll);
                Ksh[key * 36 + kc8 * 4 + i] = hh;
                Ksl[key * 36 + kc8 * 4 + i] = ll;
                Vs[key * 36 + kc8 * 4 + i] = tf32_rna(va[i]);
            }
        }
#pragma unroll
        for (int p = 0; p < 8; p++) {
            int row = br + p * 16;
            float4 bvv = *(const float4*)(bbase + (size_t)row * NTOK + mt * 64 + bc * 4);
            *(float4*)(BP + row * 68 + bc * 4) = bvv;
        }
        __syncthreads();

        // QK^T: 3xTF32
        float S[8][4];
#pragma unroll
        for (int j = 0; j < 8; j++)
#pragma unroll
            for (int c = 0; c < 4; c++) S[j][c] = 0.0f;
#pragma unroll
        for (int kt = 0; kt < 4; kt++) {
            int kc = kt * 8 + tg;
#pragma unroll
            for (int j = 0; j < 8; j++) {
                int key = j * 8 + g;
                unsigned bh[2] = {Ksh[key * 36 + kc], Ksh[key * 36 + kc + 4]};
                unsigned bl[2] = {Ksl[key * 36 + kc], Ksl[key * 36 + kc + 4]};
                mma8(S[j], Qh[kt], bh);
                mma8(S[j], Qh[kt], bl);
                mma8(S[j], Ql[kt], bh);
            }
        }
        // bias add (fp32 from smem)
#pragma unroll
        for (int j = 0; j < 8; j++) {
            int r = w * 16 + g;
            float2 b0 = *(const float2*)(BP + r * 68 + j * 8 + tg * 2);
            float2 b1 = *(const float2*)(BP + (r + 8) * 68 + j * 8 + tg * 2);
            S[j][0] += b0.x; S[j][1] += b0.y;
            S[j][2] += b1.x; S[j][3] += b1.y;
        }
        // online softmax (rows g, g+8; quad shfl reductions)
        float mx0 = -INFINITY, mx1 = -INFINITY;
#pragma unroll
        for (int j = 0; j < 8; j++) {
            mx0 = fmaxf(mx0, fmaxf(S[j][0], S[j][1]));
            mx1 = fmaxf(mx1, fmaxf(S[j][2], S[j][3]));
        }
        mx0 = fmaxf(mx0, __shfl_xor_sync(0xffffffffu, mx0, 1));
        mx0 = fmaxf(mx0, __shfl_xor_sync(0xffffffffu, mx0, 2));
        mx1 = fmaxf(mx1, __shfl_xor_sync(0xffffffffu, mx1, 1));
        mx1 = fmaxf(mx1, __shfl_xor_sync(0xffffffffu, mx1, 2));
        float mn0 = fmaxf(m0, mx0), mn1 = fmaxf(m1, mx1);
        float alpha0 = __expf(m0 - mn0), alpha1 = __expf(m1 - mn1);
        m0 = mn0; m1 = mn1;
        float rs0 = 0.0f, rs1 = 0.0f;
#pragma unroll
        for (int j = 0; j < 8; j++) {
            S[j][0] = __expf(S[j][0] - mn0);
            S[j][1] = __expf(S[j][1] - mn0);
            S[j][2] = __expf(S[j][2] - mn1);
            S[j][3] = __expf(S[j][3] - mn1);
            rs0 += S[j][0] + S[j][1];
            rs1 += S[j][2] + S[j][3];
        }
        rs0 += __shfl_xor_sync(0xffffffffu, rs0, 1);
        rs0 += __shfl_xor_sync(0xffffffffu, rs0, 2);
        rs1 += __shfl_xor_sync(0xffffffffu, rs1, 1);
        rs1 += __shfl_xor_sync(0xffffffffu, rs1, 2);
        l0 = l0 * alpha0 + rs0;
        l1 = l1 * alpha1 + rs1;
#pragma unroll
        for (int j = 0; j < 4; j++) {
            O[j][0] *= alpha0; O[j][1] *= alpha0;
            O[j][2] *= alpha1; O[j][3] *= alpha1;
        }
        __syncthreads();  // bias reads done before P overwrite
        // store P (tf32 bits) into BP
#pragma unroll
        for (int j = 0; j < 8; j++) {
            int r = w * 16 + g;
            uint2 p0 = make_uint2(tf32_rna(S[j][0]), tf32_rna(S[j][1]));
            uint2 p1 = make_uint2(tf32_rna(S[j][2]), tf32_rna(S[j][3]));
            *(uint2*)(BPu + r * 68 + j * 8 + tg * 2) = p0;
            *(uint2*)(BPu + (r + 8) * 68 + j * 8 + tg * 2) = p1;
        }
        __syncthreads();
        // P @ V accumulate (TF32 1x)
#pragma unroll
        for (int kt = 0; kt < 8; kt++) {
            int kc = kt * 8 + tg;
            int r = w * 16 + g;
            unsigned a[4] = {BPu[r * 68 + kc], BPu[(r + 8) * 68 + kc],
                             BPu[r * 68 + kc + 4], BPu[(r + 8) * 68 + kc + 4]};
#pragma unroll
            for (int j = 0; j < 4; j++) {
                unsigned bb[2] = {Vs[kc * 36 + j * 8 + g], Vs[(kc + 4) * 36 + j * 8 + g]};
                mma8(O[j], a, bb);
            }
        }
    }
    // epilogue
    float inv0 = 1.0f / l0, inv1 = 1.0f / l1;
    int q0r = qt * 128 + w * 16 + g;
    float* ob = g_attn + ((size_t)b * NTOK + q0r) * DIMC + h * HD;
#pragma unroll
    for (int j = 0; j < 4; j++) {
        *(float2*)(ob + j * 8 + tg * 2) = make_float2(O[j][0] * inv0, O[j][1] * inv0);
        *(float2*)(ob + 8 * DIMC + j * 8 + tg * 2) = make_float2(O[j][2] * inv1, O[j][3] * inv1);
    }
}

// ---------------- launcher ---------------------------------------------------
extern "C" void kernel_launch(void* const* d_in, const int* in_sizes, int n_in,
                              void* d_out, int out_size) {
    const float* x      = (const float*)d_in[0];
    const int*   rpi    = (const int*)d_in[3];
    const float* table  = (const float*)d_in[4];
    const float* qkv_w  = (const float*)d_in[5];
    const float* qkv_b  = (const float*)d_in[6];
    const float* proj_w = (const float*)d_in[7];
    const float* proj_b = (const float*)d_in[8];
    const float* temp   = (const float*)d_in[9];
    const float* qe     = (const float*)d_in[10];
    const float* fc1w   = (const float*)d_in[11];
    const float* fc1b   = (const float*)d_in[12];
    const float* fc2w   = (const float*)d_in[13];
    const float* fc2b   = (const float*)d_in[14];
    float* out = (float*)d_out;

    float* p_qkv;  cudaGetSymbolAddress((void**)&p_qkv,  g_qkv);
    float* p_attn; cudaGetSymbolAddress((void**)&p_attn, g_attn);

    static int smem_set = 0;
    if (!smem_set) {
        cudaFuncSetAttribute(attn3_kernel, cudaFuncAttributeMaxDynamicSharedMemorySize,
                             ATTN_SMEM);
        smem_set = 1;
    }

    scale_kernel<<<1, 32>>>(temp);
    cpb_kernel<<<TABLE_SZ, 512>>>(table, fc1w, fc1b, fc2w, fc2b);
    bias_kernel<<<NTOK, 256>>>(rpi);
    {
        dim3 grid(3 * DIMC / 128, BATCH * NTOK / 128);
        gemm3_tf32<<<grid, 256>>>(x, qkv_w, qkv_b, p_qkv,
                                  BATCH * NTOK, 3 * DIMC, DIMC);
    }
    reorg_kernel<<<BATCH * NTOK * NH / 8, 256>>>(qe);
    {
        dim3 grid(BATCH, NTOK / 128, NH);
        attn3_kernel<<<grid, 256, ATTN_SMEM>>>();
    }
    {
        dim3 grid(DIMC / 128, BATCH * NTOK / 128);
        gemm3_tf32<<<grid, 256>>>(p_attn, proj_w, proj_b, out,
                                  BATCH * NTOK, DIMC, DIMC);
    }
}

// round 3
// speedup vs baseline: 2.4791x; 1.1784x over previous
#include <cuda_runtime.h>
#include <math.h>

// Problem constants
#define BATCH 8
#define NTOK 1024
#define DIMC 512
#define NH 16
#define HD 32
#define TABLE_SZ 3969
#define SEQ_SCALE 6.93147180559945309f  // ln(1024)

// ---------------- scratch (device globals; no allocation allowed) -------------
__device__ float g_scale[NH];
__device__ float g_t[TABLE_SZ * NH];
__device__ float g_bias[NH * NTOK * NTOK];          // [h][n][m] 64MB
__device__ float g_qkv[BATCH * NTOK * 3 * DIMC];    // 50MB
__device__ float g_q[BATCH * NH * NTOK * HD];
__device__ float g_k[BATCH * NH * NTOK * HD];
__device__ float g_v[BATCH * NH * NTOK * HD];
__device__ float g_attn[BATCH * NTOK * DIMC];
__device__ unsigned g_wh[(3 * DIMC + DIMC) * DIMC]; // pre-split W hi (qkv then proj)
__device__ unsigned g_wl[(3 * DIMC + DIMC) * DIMC]; // pre-split W lo

// ---------------- tf32 / cp.async helpers ------------------------------------
__device__ __forceinline__ unsigned tf32_rna(float x) {
    unsigned r; asm("cvt.rna.tf32.f32 %0, %1;" : "=r"(r) : "f"(x)); return r;
}
__device__ __forceinline__ void tf32_split(float x, unsigned& hi, unsigned& lo) {
    hi = tf32_rna(x);
    lo = tf32_rna(x - __uint_as_float(hi));
}
__device__ __forceinline__ void mma8(float* c, const unsigned* a, const unsigned* b) {
    asm volatile("mma.sync.aligned.m16n8k8.row.col.f32.tf32.tf32.f32 "
                 "{%0,%1,%2,%3}, {%4,%5,%6,%7}, {%8,%9}, {%0,%1,%2,%3};"
                 : "+f"(c[0]), "+f"(c[1]), "+f"(c[2]), "+f"(c[3])
                 : "r"(a[0]), "r"(a[1]), "r"(a[2]), "r"(a[3]),
                   "r"(b[0]), "r"(b[1]));
}
__device__ __forceinline__ void cp16(void* sdst, const void* gsrc) {
    unsigned u = (unsigned)__cvta_generic_to_shared(sdst);
    asm volatile("cp.async.ca.shared.global [%0], [%1], 16;" :: "r"(u), "l"(gsrc));
}
#define CP_COMMIT() asm volatile("cp.async.commit_group;")
#define CP_WAIT(n)  asm volatile("cp.async.wait_group %0;" :: "n"(n))

// ---------------- kernel 1: scale = softplus(temperature) * ln(N) ------------
__global__ void scale_kernel(const float* __restrict__ temp) {
    int h = threadIdx.x;
    if (h < NH) {
        float t = temp[h];
        float sp = (t > 20.0f) ? t : log1pf(expf(t));
        g_scale[h] = sp * SEQ_SCALE;
    }
}

// ---------------- kernel: pre-split weights into tf32 hi/lo -------------------
__global__ void wsplit_kernel(const float* __restrict__ qkvw,
                              const float* __restrict__ projw) {
    int i = blockIdx.x * 256 + threadIdx.x;
    int nq = 3 * DIMC * DIMC;
    int np = DIMC * DIMC;
    if (i < nq) {
        unsigned h, l; tf32_split(qkvw[i], h, l);
        g_wh[i] = h; g_wl[i] = l;
    } else if (i < nq + np) {
        unsigned h, l; tf32_split(projw[i - nq], h, l);
        g_wh[i] = h; g_wl[i] = l;
    }
}

// ---------------- kernel 2: CPB MLP  t[r][h] ---------------------------------
__global__ void cpb_kernel(const float* __restrict__ table,
                           const float* __restrict__ fc1w,
                           const float* __restrict__ fc1b,
                           const float* __restrict__ fc2w,
                           const float* __restrict__ fc2b) {
    __shared__ float hid[512];
    int r = blockIdx.x;
    int j = threadIdx.x;
    float c0 = table[r * 2 + 0];
    float c1 = table[r * 2 + 1];
    float hv = c0 * fc1w[j * 2 + 0] + c1 * fc1w[j * 2 + 1] + fc1b[j];
    hid[j] = fmaxf(hv, 0.0f);
    __syncthreads();
    int w = j >> 5;
    int lane = j & 31;
    float acc = 0.0f;
#pragma unroll
    for (int kk = lane; kk < 512; kk += 32) acc += hid[kk] * fc2w[w * 512 + kk];
#pragma unroll
    for (int off = 16; off >= 1; off >>= 1) acc += __shfl_xor_sync(0xffffffffu, acc, off);
    if (lane == 0) g_t[r * NH + w] = acc + fc2b[w];
}

// ---------------- kernel 3: bias gather  bias[h][n][m] = t[rpi[n][m]][h] -----
__global__ void bias_kernel(const int* __restrict__ rpi) {
    int n = blockIdx.x;
    for (int m = threadIdx.x; m < NTOK; m += blockDim.x) {
        int idx = rpi[n * NTOK + m];
        const float4* tp = (const float4*)(g_t + idx * NH);
        float4 t0 = tp[0], t1 = tp[1], t2 = tp[2], t3 = tp[3];
        float v[16] = {t0.x, t0.y, t0.z, t0.w, t1.x, t1.y, t1.z, t1.w,
                       t2.x, t2.y, t2.z, t2.w, t3.x, t3.y, t3.z, t3.w};
#pragma unroll
        for (int h = 0; h < NH; h++)
            g_bias[(h * NTOK + n) * NTOK + m] = v[h];
    }
}

// ---------------- 3xTF32 GEMM, cp.async 2-stage, pre-split W ------------------
// BM=BN=128, BK=16, 256 threads, 8 warps 4x2, warp tile 32x64.
// dyn smem: As[2][128][20] fp32, Whs[2][128][20] u32, Wls[2][128][20] u32
#define GEMM_SMEM (3 * 2 * 128 * 20 * 4)
__global__ __launch_bounds__(256, 2) void gemm3p(const float* __restrict__ A,
                                                 const unsigned* __restrict__ Wh,
                                                 const unsigned* __restrict__ Wl,
                                                 const float* __restrict__ bias,
                                                 float* __restrict__ C,
                                                 int M, int Nn, int K) {
    extern __shared__ float smbuf[];
    float* As = smbuf;                         // 2*2560
    unsigned* Whs = (unsigned*)(As + 2 * 2560);
    unsigned* Wls = Whs + 2 * 2560;

    int tid = threadIdx.x;
    int wid = tid >> 5, lane = tid & 31;
    int g = lane >> 2, tg = lane & 3;
    int wm = wid & 3, wn = wid >> 2;
    int m0 = blockIdx.y * 128, n0 = blockIdx.x * 128;

    // loader mapping: 512 16B-chunks per array, 2 per thread
    int lrow0 = tid >> 2, lch0 = tid & 3;          // chunk idx tid
    int lrow1 = (tid + 256) >> 2, lch1 = tid & 3;  // chunk idx tid+256

    float acc[2][8][4];
#pragma unroll
    for (int mi = 0; mi < 2; mi++)
#pragma unroll
        for (int j = 0; j < 8; j++)
#pragma unroll
            for (int c = 0; c < 4; c++) acc[mi][j][c] = 0.0f;

    int nk = K >> 4;
    // prologue: stage 0
    {
        int k0 = 0;
        cp16(&As[0 * 2560 + lrow0 * 20 + lch0 * 4], A + (size_t)(m0 + lrow0) * K + k0 + lch0 * 4);
        cp16(&As[0 * 2560 + lrow1 * 20 + lch1 * 4], A + (size_t)(m0 + lrow1) * K + k0 + lch1 * 4);
        cp16(&Whs[0 * 2560 + lrow0 * 20 + lch0 * 4], Wh + (size_t)(n0 + lrow0) * K + k0 + lch0 * 4);
        cp16(&Whs[0 * 2560 + lrow1 * 20 + lch1 * 4], Wh + (size_t)(n0 + lrow1) * K + k0 + lch1 * 4);
        cp16(&Wls[0 * 2560 + lrow0 * 20 + lch0 * 4], Wl + (size_t)(n0 + lrow0) * K + k0 + lch0 * 4);
        cp16(&Wls[0 * 2560 + lrow1 * 20 + lch1 * 4], Wl + (size_t)(n0 + lrow1) * K + k0 + lch1 * 4);
        CP_COMMIT();
    }

    for (int i = 0; i < nk; i++) {
        if (i + 1 < nk) {
            int s = (i + 1) & 1;
            int k0 = (i + 1) << 4;
            cp16(&As[s * 2560 + lrow0 * 20 + lch0 * 4], A + (size_t)(m0 + lrow0) * K + k0 + lch0 * 4);
            cp16(&As[s * 2560 + lrow1 * 20 + lch1 * 4], A + (size_t)(m0 + lrow1) * K + k0 + lch1 * 4);
            cp16(&Whs[s * 2560 + lrow0 * 20 + lch0 * 4], Wh + (size_t)(n0 + lrow0) * K + k0 + lch0 * 4);
            cp16(&Whs[s * 2560 + lrow1 * 20 + lch1 * 4], Wh + (size_t)(n0 + lrow1) * K + k0 + lch1 * 4);
            cp16(&Wls[s * 2560 + lrow0 * 20 + lch0 * 4], Wl + (size_t)(n0 + lrow0) * K + k0 + lch0 * 4);
            cp16(&Wls[s * 2560 + lrow1 * 20 + lch1 * 4], Wl + (size_t)(n0 + lrow1) * K + k0 + lch1 * 4);
            CP_COMMIT();
            CP_WAIT(1);
        } else {
            CP_WAIT(0);
        }
        __syncthreads();
        int s = i & 1;
        const float* Ab = As + s * 2560;
        const unsigned* Whb = Whs + s * 2560;
        const unsigned* Wlb = Wls + s * 2560;
#pragma unroll
        for (int kt = 0; kt < 2; kt++) {
            int kc = kt * 8 + tg;
            unsigned ah[2][4], al[2][4];
#pragma unroll
            for (int mi = 0; mi < 2; mi++) {
                int r = wm * 32 + mi * 16 + g;
                tf32_split(Ab[r * 20 + kc], ah[mi][0], al[mi][0]);
                tf32_split(Ab[(r + 8) * 20 + kc], ah[mi][1], al[mi][1]);
                tf32_split(Ab[r * 20 + kc + 4], ah[mi][2], al[mi][2]);
                tf32_split(Ab[(r + 8) * 20 + kc + 4], ah[mi][3], al[mi][3]);
            }
#pragma unroll
            for (int j = 0; j < 8; j++) {
                int col = wn * 64 + j * 8 + g;
                unsigned bh[2] = {Whb[col * 20 + kc], Whb[col * 20 + kc + 4]};
                unsigned bl[2] = {Wlb[col * 20 + kc], Wlb[col * 20 + kc + 4]};
#pragma unroll
                for (int mi = 0; mi < 2; mi++) {
                    mma8(acc[mi][j], ah[mi], bh);
                    mma8(acc[mi][j], ah[mi], bl);
                    mma8(acc[mi][j], al[mi], bh);
                }
            }
        }
        __syncthreads();
    }
    // epilogue
#pragma unroll
    for (int j = 0; j < 8; j++) {
        int col = n0 + wn * 64 + j * 8 + tg * 2;
        float2 bv = *(const float2*)(bias + col);
#pragma unroll
        for (int mi = 0; mi < 2; mi++) {
            int row = m0 + wm * 32 + mi * 16 + g;
            float2 o0 = make_float2(acc[mi][j][0] + bv.x, acc[mi][j][1] + bv.y);
            float2 o1 = make_float2(acc[mi][j][2] + bv.x, acc[mi][j][3] + bv.y);
            *(float2*)(C + (size_t)row * Nn + col) = o0;
            *(float2*)(C + (size_t)(row + 8) * Nn + col) = o1;
        }
    }
}

// ---------------- reorg: split qkv, normalize q/k, repack to [b,h,n,d] -------
__global__ void reorg_kernel(const float* __restrict__ qe) {
    int wg = blockIdx.x * 8 + (threadIdx.x >> 5);
    int lane = threadIdx.x & 31;
    int h = wg & 15;
    int bn = wg >> 4;
    int b = bn >> 10;
    int n = bn & 1023;
    const float* base = g_qkv + (size_t)bn * (3 * DIMC);
    float q = base[h * HD + lane];
    float k = base[DIMC + h * HD + lane];
    float v = base[2 * DIMC + h * HD + lane];

    float s = q * q;
#pragma unroll
    for (int off = 16; off >= 1; off >>= 1) s += __shfl_xor_sync(0xffffffffu, s, off);
    float qn = q / fmaxf(sqrtf(s), 1e-12f);
    qn = (qn + qe[h * HD + lane]) * g_scale[h];

    s = k * k;
#pragma unroll
    for (int off = 16; off >= 1; off >>= 1) s += __shfl_xor_sync(0xffffffffu, s, off);
    float kn = k / fmaxf(sqrtf(s), 1e-12f);

    size_t idx = ((size_t)(b * NH + h) * NTOK + n) * HD + lane;
    g_q[idx] = qn;
    g_k[idx] = kn;
    g_v[idx] = v;
}

// ---------------- attention v3: cp.async K/V pipeline -------------------------
// grid (B, N/128, H), 256 threads, 128 queries/block, key tiles 64.
// dyn smem: Kraw[2][64][36] f32, Vraw[2][64][36] f32,
//           Ksh[64][36] u32, Ksl[64][36] u32, Vs[64][36] u32, BP[128][68] f32
#define ATTN_SMEM ((2 * 64 * 36 * 2 + 3 * 64 * 36 + 128 * 68) * 4)
__global__ __launch_bounds__(256, 2) void attn3_kernel() {
    extern __shared__ float sm[];
    float* Kraw = sm;                       // 2*2304
    float* Vraw = Kraw + 2 * 2304;          // 2*2304
    unsigned* Ksh = (unsigned*)(Vraw + 2 * 2304);
    unsigned* Ksl = Ksh + 2304;
    unsigned* Vs = Ksl + 2304;
    float* BP = (float*)(Vs + 2304);
    unsigned* BPu = (unsigned*)BP;

    int b = blockIdx.x, qt = blockIdx.y, h = blockIdx.z;
    int tid = threadIdx.x;
    int w = tid >> 5, lane = tid & 31;
    int g = lane >> 2, tg = lane & 3;

    const float* qb = g_q + ((size_t)(b * NH + h) * NTOK + qt * 128) * HD;
    const float* kbase = g_k + (size_t)(b * NH + h) * NTOK * HD;
    const float* vbase = g_v + (size_t)(b * NH + h) * NTOK * HD;
    const float* bbase = g_bias + ((size_t)h * NTOK + qt * 128) * NTOK;

    // loader mapping for K/V tiles: 512 16B-chunks, 2 per thread
    int krow0 = tid >> 3, kch0 = tid & 7;
    int krow1 = (tid + 256) >> 3, kch1 = tid & 7;

    // prologue: stage 0 K/V
    cp16(&Kraw[0 * 2304 + krow0 * 36 + kch0 * 4], kbase + (size_t)krow0 * HD + kch0 * 4);
    cp16(&Kraw[0 * 2304 + krow1 * 36 + kch1 * 4], kbase + (size_t)krow1 * HD + kch1 * 4);
    cp16(&Vraw[0 * 2304 + krow0 * 36 + kch0 * 4], vbase + (size_t)krow0 * HD + kch0 * 4);
    cp16(&Vraw[0 * 2304 + krow1 * 36 + kch1 * 4], vbase + (size_t)krow1 * HD + kch1 * 4);
    CP_COMMIT();

    // Q fragments (persist in registers), 3xTF32 split
    unsigned Qh[4][4], Ql[4][4];
#pragma unroll
    for (int kt = 0; kt < 4; kt++) {
        int c = kt * 8 + tg;
        int r = w * 16 + g;
        tf32_split(qb[r * HD + c], Qh[kt][0], Ql[kt][0]);
        tf32_split(qb[(r + 8) * HD + c], Qh[kt][1], Ql[kt][1]);
        tf32_split(qb[r * HD + c + 4], Qh[kt][2], Ql[kt][2]);
        tf32_split(qb[(r + 8) * HD + c + 4], Qh[kt][3], Ql[kt][3]);
    }

    float m0 = -INFINITY, m1 = -INFINITY, l0 = 0.0f, l1 = 0.0f;
    float O[4][4];
#pragma unroll
    for (int j = 0; j < 4; j++)
#pragma unroll
        for (int c = 0; c < 4; c++) O[j][c] = 0.0f;

    int bc = tid & 15, br = tid >> 4;   // bias loaders
    int skey = tid >> 3, sc4 = (tid & 7) * 4;  // split-phase mapping

    for (int mt = 0; mt < 16; mt++) {
        if (mt + 1 < 16) {
            int s = (mt + 1) & 1;
            const float* kb = kbase + (size_t)(mt + 1) * 64 * HD;
            const float* vb = vbase + (size_t)(mt + 1) * 64 * HD;
            cp16(&Kraw[s * 2304 + krow0 * 36 + kch0 * 4], kb + (size_t)krow0 * HD + kch0 * 4);
            cp16(&Kraw[s * 2304 + krow1 * 36 + kch1 * 4], kb + (size_t)krow1 * HD + kch1 * 4);
            cp16(&Vraw[s * 2304 + krow0 * 36 + kch0 * 4], vb + (size_t)krow0 * HD + kch0 * 4);
            cp16(&Vraw[s * 2304 + krow1 * 36 + kch1 * 4], vb + (size_t)krow1 * HD + kch1 * 4);
            CP_COMMIT();
            CP_WAIT(1);
        } else {
            CP_WAIT(0);
        }
        __syncthreads();  // staging ready; prior PV done before split/bias overwrite
        // split phase: Kraw -> Ksh/Ksl, Vraw -> Vs (tf32)
        {
            int s = mt & 1;
#pragma unroll
            for (int p = 0; p < 2; p++) {
                int key = skey + p * 32;
                float4 kv = *(const float4*)&Kraw[s * 2304 + key * 36 + sc4];
                float4 vv = *(const float4*)&Vraw[s * 2304 + key * 36 + sc4];
                float ka[4] = {kv.x, kv.y, kv.z, kv.w};
                float va[4] = {vv.x, vv.y, vv.z, vv.w};
#pragma unroll
                for (int i = 0; i < 4; i++) {
                    unsigned hh, ll;
                    tf32_split(ka[i], hh, ll);
                    Ksh[key * 36 + sc4 + i] = hh;
                    Ksl[key * 36 + sc4 + i] = ll;
                    Vs[key * 36 + sc4 + i] = tf32_rna(va[i]);
                }
            }
        }
        // bias load into BP
#pragma unroll
        for (int p = 0; p < 8; p++) {
            int row = br + p * 16;
            float4 bvv = *(const float4*)(bbase + (size_t)row * NTOK + mt * 64 + bc * 4);
            *(float4*)(BP + row * 68 + bc * 4) = bvv;
        }
        __syncthreads();

        // QK^T: 3xTF32
        float S[8][4];
#pragma unroll
        for (int j = 0; j < 8; j++)
#pragma unroll
            for (int c = 0; c < 4; c++) S[j][c] = 0.0f;
#pragma unroll
        for (int kt = 0; kt < 4; kt++) {
            int kc = kt * 8 + tg;
#pragma unroll
            for (int j = 0; j < 8; j++) {
                int key = j * 8 + g;
                unsigned bh[2] = {Ksh[key * 36 + kc], Ksh[key * 36 + kc + 4]};
                unsigned bl[2] = {Ksl[key * 36 + kc], Ksl[key * 36 + kc + 4]};
                mma8(S[j], Qh[kt], bh);
                mma8(S[j], Qh[kt], bl);
                mma8(S[j], Ql[kt], bh);
            }
        }
        // bias add
#pragma unroll
        for (int j = 0; j < 8; j++) {
            int r = w * 16 + g;
            float2 b0 = *(const float2*)(BP + r * 68 + j * 8 + tg * 2);
            float2 b1 = *(const float2*)(BP + (r + 8) * 68 + j * 8 + tg * 2);
            S[j][0] += b0.x; S[j][1] += b0.y;
            S[j][2] += b1.x; S[j][3] += b1.y;
        }
        // online softmax
        float mx0 = -INFINITY, mx1 = -INFINITY;
#pragma unroll
        for (int j = 0; j < 8; j++) {
            mx0 = fmaxf(mx0, fmaxf(S[j][0], S[j][1]));
            mx1 = fmaxf(mx1, fmaxf(S[j][2], S[j][3]));
        }
        mx0 = fmaxf(mx0, __shfl_xor_sync(0xffffffffu, mx0, 1));
        mx0 = fmaxf(mx0, __shfl_xor_sync(0xffffffffu, mx0, 2));
        mx1 = fmaxf(mx1, __shfl_xor_sync(0xffffffffu, mx1, 1));
        mx1 = fmaxf(mx1, __shfl_xor_sync(0xffffffffu, mx1, 2));
        float mn0 = fmaxf(m0, mx0), mn1 = fmaxf(m1, mx1);
        float alpha0 = __expf(m0 - mn0), alpha1 = __expf(m1 - mn1);
        m0 = mn0; m1 = mn1;
        float rs0 = 0.0f, rs1 = 0.0f;
#pragma unroll
        for (int j = 0; j < 8; j++) {
            S[j][0] = __expf(S[j][0] - mn0);
            S[j][1] = __expf(S[j][1] - mn0);
            S[j][2] = __expf(S[j][2] - mn1);
            S[j][3] = __expf(S[j][3] - mn1);
            rs0 += S[j][0] + S[j][1];
            rs1 += S[j][2] + S[j][3];
        }
        rs0 += __shfl_xor_sync(0xffffffffu, rs0, 1);
        rs0 += __shfl_xor_sync(0xffffffffu, rs0, 2);
        rs1 += __shfl_xor_sync(0xffffffffu, rs1, 1);
        rs1 += __shfl_xor_sync(0xffffffffu, rs1, 2);
        l0 = l0 * alpha0 + rs0;
        l1 = l1 * alpha1 + rs1;
#pragma unroll
        for (int j = 0; j < 4; j++) {
            O[j][0] *= alpha0; O[j][1] *= alpha0;
            O[j][2] *= alpha1; O[j][3] *= alpha1;
        }
        __syncthreads();  // bias reads done before P overwrite
        // store P (tf32 bits) into BP
#pragma unroll
        for (int j = 0; j < 8; j++) {
            int r = w * 16 + g;
            uint2 p0 = make_uint2(tf32_rna(S[j][0]), tf32_rna(S[j][1]));
            uint2 p1 = make_uint2(tf32_rna(S[j][2]), tf32_rna(S[j][3]));
            *(uint2*)(BPu + r * 68 + j * 8 + tg * 2) = p0;
            *(uint2*)(BPu + (r + 8) * 68 + j * 8 + tg * 2) = p1;
        }
        __syncthreads();
        // P @ V accumulate (TF32 1x)
#pragma unroll
        for (int kt = 0; kt < 8; kt++) {
            int kc = kt * 8 + tg;
            int r = w * 16 + g;
            unsigned a[4] = {BPu[r * 68 + kc], BPu[(r + 8) * 68 + kc],
                             BPu[r * 68 + kc + 4], BPu[(r + 8) * 68 + kc + 4]};
#pragma unroll
            for (int j = 0; j < 4; j++) {
                unsigned bb[2] = {Vs[kc * 36 + j * 8 + g], Vs[(kc + 4) * 36 + j * 8 + g]};
                mma8(O[j], a, bb);
            }
        }
    }
    // epilogue
    float inv0 = 1.0f / l0, inv1 = 1.0f / l1;
    int q0r = qt * 128 + w * 16 + g;
    float* ob = g_attn + ((size_t)b * NTOK + q0r) * DIMC + h * HD;
#pragma unroll
    for (int j = 0; j < 4; j++) {
        *(float2*)(ob + j * 8 + tg * 2) = make_float2(O[j][0] * inv0, O[j][1] * inv0);
        *(float2*)(ob + 8 * DIMC + j * 8 + tg * 2) = make_float2(O[j][2] * inv1, O[j][3] * inv1);
    }
}

// ---------------- launcher ---------------------------------------------------
extern "C" void kernel_launch(void* const* d_in, const int* in_sizes, int n_in,
                              void* d_out, int out_size) {
    const float* x      = (const float*)d_in[0];
    const int*   rpi    = (const int*)d_in[3];
    const float* table  = (const float*)d_in[4];
    const float* qkv_w  = (const float*)d_in[5];
    const float* qkv_b  = (const float*)d_in[6];
    const float* proj_w = (const float*)d_in[7];
    const float* proj_b = (const float*)d_in[8];
    const float* temp   = (const float*)d_in[9];
    const float* qe     = (const float*)d_in[10];
    const float* fc1w   = (const float*)d_in[11];
    const float* fc1b   = (const float*)d_in[12];
    const float* fc2w   = (const float*)d_in[13];
    const float* fc2b   = (const float*)d_in[14];
    float* out = (float*)d_out;

    float* p_qkv;  cudaGetSymbolAddress((void**)&p_qkv,  g_qkv);
    float* p_attn; cudaGetSymbolAddress((void**)&p_attn, g_attn);
    unsigned* p_wh; cudaGetSymbolAddress((void**)&p_wh, g_wh);
    unsigned* p_wl; cudaGetSymbolAddress((void**)&p_wl, g_wl);

    static int attr_set = 0;
    if (!attr_set) {
        cudaFuncSetAttribute(attn3_kernel, cudaFuncAttributeMaxDynamicSharedMemorySize,
                             ATTN_SMEM);
        cudaFuncSetAttribute(gemm3p, cudaFuncAttributeMaxDynamicSharedMemorySize,
                             GEMM_SMEM);
        attr_set = 1;
    }

    scale_kernel<<<1, 32>>>(temp);
    wsplit_kernel<<<(4 * DIMC * DIMC + 255) / 256, 256>>>(qkv_w, proj_w);
    cpb_kernel<<<TABLE_SZ, 512>>>(table, fc1w, fc1b, fc2w, fc2b);
    bias_kernel<<<NTOK, 256>>>(rpi);
    {
        dim3 grid(3 * DIMC / 128, BATCH * NTOK / 128);
        gemm3p<<<grid, 256, GEMM_SMEM>>>(x, p_wh, p_wl, qkv_b, p_qkv,
                                         BATCH * NTOK, 3 * DIMC, DIMC);
    }
    reorg_kernel<<<BATCH * NTOK * NH / 8, 256>>>(qe);
    {
        dim3 grid(BATCH, NTOK / 128, NH);
        attn3_kernel<<<grid, 256, ATTN_SMEM>>>();
    }
    {
        dim3 grid(DIMC / 128, BATCH * NTOK / 128);
        gemm3p<<<grid, 256, GEMM_SMEM>>>(p_attn, p_wh + 3 * DIMC * DIMC,
                                         p_wl + 3 * DIMC * DIMC, proj_b, out,
                                         BATCH * NTOK, DIMC, DIMC);
    }
}